// round 2
// baseline (speedup 1.0000x reference)
#include <cuda_runtime.h>

// Problem constants
#define IMH   64
#define IMW   64
#define HW    4096          // 64*64
#define CIN   256
#define COUT  256
#define KKTAP 9             // 3x3
#define BATCH 4
#define KDIM  (CIN * KKTAP) // 2304
#define NDIM  (BATCH * HW)  // 16384

// Scratch: deformable im2col column matrix, [KDIM][NDIM] row-major,
// k = c*9 + kk  (matches weight [O][C][3][3] flattened as A[o][c*9+kk])
__device__ float g_cols[(size_t)KDIM * NDIM];

// ---------------------------------------------------------------------------
// Kernel 1: bilinear deformable gather (im2col)
// One thread per (b, kk, hw) tap; loops over C=256 channels reusing the
// 4 corner indices/weights computed once.
// ---------------------------------------------------------------------------
__global__ __launch_bounds__(256) void im2col_deform_kernel(
    const float* __restrict__ x,       // [B, CIN, H, W]
    const float* __restrict__ offset)  // [B, 2*KK, H, W], (y,x) per tap
{
    int t  = blockIdx.x * blockDim.x + threadIdx.x;   // 0 .. B*KK*HW-1
    int hw = t & (HW - 1);
    int r  = t >> 12;            // b*KK + kk
    int kk = r % KKTAP;
    int b  = r / KKTAP;
    int ho = hw >> 6;
    int wo = hw & 63;

    const float* offb = offset + (size_t)b * (2 * KKTAP) * HW;
    float offy = offb[(2 * kk)     * HW + hw];
    float offx = offb[(2 * kk + 1) * HW + hw];

    // py = ho*stride - pad + (kk/3)*dil + offy ; same for x
    float py = (float)(ho - 1 + kk / 3) + offy;
    float px = (float)(wo - 1 + kk % 3) + offx;

    float fy = floorf(py), fx = floorf(px);
    float ly = py - fy,    lx = px - fx;
    int y0 = (int)fy, x0 = (int)fx;
    int y1 = y0 + 1,  x1 = x0 + 1;

    float wy0 = 1.0f - ly, wy1 = ly;
    float wx0 = 1.0f - lx, wx1 = lx;

    bool vy0 = (y0 >= 0) & (y0 < IMH);
    bool vy1 = (y1 >= 0) & (y1 < IMH);
    bool vx0 = (x0 >= 0) & (x0 < IMW);
    bool vx1 = (x1 >= 0) & (x1 < IMW);

    float w00 = wy0 * wx0 * (float)(vy0 & vx0);
    float w01 = wy0 * wx1 * (float)(vy0 & vx1);
    float w10 = wy1 * wx0 * (float)(vy1 & vx0);
    float w11 = wy1 * wx1 * (float)(vy1 & vx1);

    int cy0 = min(max(y0, 0), IMH - 1);
    int cy1 = min(max(y1, 0), IMH - 1);
    int cx0 = min(max(x0, 0), IMW - 1);
    int cx1 = min(max(x1, 0), IMW - 1);

    int i00 = cy0 * IMW + cx0;
    int i01 = cy0 * IMW + cx1;
    int i10 = cy1 * IMW + cx0;
    int i11 = cy1 * IMW + cx1;

    const float* xb = x + (size_t)b * CIN * HW;
    // cols[(c*9+kk)][b*HW + hw]
    float* outp = g_cols + (size_t)kk * NDIM + (size_t)b * HW + hw;

    #pragma unroll 4
    for (int c = 0; c < CIN; c++) {
        const float* xc = xb + (size_t)c * HW;
        float v = w00 * xc[i00] + w01 * xc[i01] + w10 * xc[i10] + w11 * xc[i11];
        outp[(size_t)c * (KKTAP * NDIM)] = v;
    }
}

// ---------------------------------------------------------------------------
// Kernel 2: SGEMM  C[M=256][N=16384] = A[256][2304] * g_cols[2304][16384] + bias
// 128x128 block tile, BK=16, 256 threads, 8x8 micro-tile per thread.
// Epilogue writes out[b][o][hw] layout directly.
// ---------------------------------------------------------------------------
#define BM 128
#define BN 128
#define BK 16

__global__ __launch_bounds__(256) void gemm_kernel(
    const float* __restrict__ A,     // weight, [COUT][KDIM] row-major
    const float* __restrict__ bias,  // [COUT]
    float* __restrict__ out)         // [B][COUT][HW]
{
    __shared__ float As[BK][BM];     // transposed A tile
    __shared__ float Bs[BK][BN];

    const int bm  = blockIdx.y * BM;
    const int bn  = blockIdx.x * BN;
    const int tid = threadIdx.x;
    const int tx  = tid & 15;        // 0..15  -> n
    const int ty  = tid >> 4;        // 0..15  -> m

    float acc[8][8];
    #pragma unroll
    for (int i = 0; i < 8; i++)
        #pragma unroll
        for (int j = 0; j < 8; j++) acc[i][j] = 0.0f;

    const float* Bmat = g_cols;

    for (int k0 = 0; k0 < KDIM; k0 += BK) {
        // Load A tile: 128 rows x 16 k -> 512 float4, 2 per thread.
        #pragma unroll
        for (int u = 0; u < 2; u++) {
            int id  = u * 256 + tid;       // 0..511
            int row = id >> 2;             // 0..127
            int kq  = id & 3;              // which float4 within the 16 k
            float4 v = *reinterpret_cast<const float4*>(
                &A[(size_t)(bm + row) * KDIM + k0 + kq * 4]);
            As[kq * 4 + 0][row] = v.x;
            As[kq * 4 + 1][row] = v.y;
            As[kq * 4 + 2][row] = v.z;
            As[kq * 4 + 3][row] = v.w;
        }
        // Load B tile: 16 k x 128 n -> 512 float4, 2 per thread, coalesced.
        #pragma unroll
        for (int u = 0; u < 2; u++) {
            int id = u * 256 + tid;        // 0..511
            int kr = id >> 5;              // 0..15
            int nq = id & 31;              // float4 index within row
            float4 v = *reinterpret_cast<const float4*>(
                &Bmat[(size_t)(k0 + kr) * NDIM + bn + nq * 4]);
            *reinterpret_cast<float4*>(&Bs[kr][nq * 4]) = v;
        }
        __syncthreads();

        #pragma unroll
        for (int k = 0; k < BK; k++) {
            float4 a0 = *reinterpret_cast<const float4*>(&As[k][ty * 8]);
            float4 a1 = *reinterpret_cast<const float4*>(&As[k][ty * 8 + 4]);
            float4 b0 = *reinterpret_cast<const float4*>(&Bs[k][tx * 8]);
            float4 b1 = *reinterpret_cast<const float4*>(&Bs[k][tx * 8 + 4]);
            float a[8] = {a0.x, a0.y, a0.z, a0.w, a1.x, a1.y, a1.z, a1.w};
            float bb[8] = {b0.x, b0.y, b0.z, b0.w, b1.x, b1.y, b1.z, b1.w};
            #pragma unroll
            for (int i = 0; i < 8; i++)
                #pragma unroll
                for (int j = 0; j < 8; j++)
                    acc[i][j] = fmaf(a[i], bb[j], acc[i][j]);
        }
        __syncthreads();
    }

    // Epilogue: n = b*4096 + hw ; tile (BN=128) never crosses a batch boundary.
    const int b_img = bn >> 12;
    const int hw0   = (bn & (HW - 1)) + tx * 8;

    #pragma unroll
    for (int i = 0; i < 8; i++) {
        int m = bm + ty * 8 + i;
        float bv = __ldg(&bias[m]);
        float* orow = out + ((size_t)b_img * COUT + m) * HW + hw0;
        float4 v0 = make_float4(acc[i][0] + bv, acc[i][1] + bv,
                                acc[i][2] + bv, acc[i][3] + bv);
        float4 v1 = make_float4(acc[i][4] + bv, acc[i][5] + bv,
                                acc[i][6] + bv, acc[i][7] + bv);
        *reinterpret_cast<float4*>(orow)     = v0;
        *reinterpret_cast<float4*>(orow + 4) = v1;
    }
}

// ---------------------------------------------------------------------------
extern "C" void kernel_launch(void* const* d_in, const int* in_sizes, int n_in,
                              void* d_out, int out_size)
{
    const float* x      = (const float*)d_in[0];  // [4,256,64,64]
    const float* offset = (const float*)d_in[1];  // [4,18,64,64]
    const float* weight = (const float*)d_in[2];  // [256,256,3,3]
    const float* bias   = (const float*)d_in[3];  // [256]
    float* out = (float*)d_out;                   // [4,256,64,64]

    // B*KK*HW = 147456 taps
    im2col_deform_kernel<<<(BATCH * KKTAP * HW) / 256, 256>>>(x, offset);

    dim3 grid(NDIM / BN, COUT / BM);  // (128, 2)
    gemm_kernel<<<grid, 256>>>(weight, bias, out);
}

// round 3
// speedup vs baseline: 1.0020x; 1.0020x over previous
#include <cuda_runtime.h>

// Problem constants
#define IMH   64
#define IMW   64
#define HW    4096          // 64*64
#define CIN   256
#define COUT  256
#define KKTAP 9             // 3x3
#define BATCH 4
#define KDIM  (CIN * KKTAP) // 2304
#define NDIM  (BATCH * HW)  // 16384

// Scratch: deformable im2col column matrix, [KDIM][NDIM] row-major,
// k = c*9 + kk  (matches weight [O][C][3][3] flattened as A[o][c*9+kk])
__device__ float g_cols[(size_t)KDIM * NDIM];

// ---------------------------------------------------------------------------
// Kernel 1: bilinear deformable gather (im2col)
// One thread per (b, kk, hw) tap; loops over C=256 channels reusing the
// 4 corner indices/weights computed once.
// ---------------------------------------------------------------------------
__global__ __launch_bounds__(256) void im2col_deform_kernel(
    const float* __restrict__ x,       // [B, CIN, H, W]
    const float* __restrict__ offset)  // [B, 2*KK, H, W], (y,x) per tap
{
    int t  = blockIdx.x * blockDim.x + threadIdx.x;   // 0 .. B*KK*HW-1
    int hw = t & (HW - 1);
    int r  = t >> 12;            // b*KK + kk
    int kk = r % KKTAP;
    int b  = r / KKTAP;
    int ho = hw >> 6;
    int wo = hw & 63;

    const float* offb = offset + (size_t)b * (2 * KKTAP) * HW;
    float offy = offb[(2 * kk)     * HW + hw];
    float offx = offb[(2 * kk + 1) * HW + hw];

    // py = ho*stride - pad + (kk/3)*dil + offy ; same for x
    float py = (float)(ho - 1 + kk / 3) + offy;
    float px = (float)(wo - 1 + kk % 3) + offx;

    float fy = floorf(py), fx = floorf(px);
    float ly = py - fy,    lx = px - fx;
    int y0 = (int)fy, x0 = (int)fx;
    int y1 = y0 + 1,  x1 = x0 + 1;

    float wy0 = 1.0f - ly, wy1 = ly;
    float wx0 = 1.0f - lx, wx1 = lx;

    bool vy0 = (y0 >= 0) & (y0 < IMH);
    bool vy1 = (y1 >= 0) & (y1 < IMH);
    bool vx0 = (x0 >= 0) & (x0 < IMW);
    bool vx1 = (x1 >= 0) & (x1 < IMW);

    float w00 = wy0 * wx0 * (float)(vy0 & vx0);
    float w01 = wy0 * wx1 * (float)(vy0 & vx1);
    float w10 = wy1 * wx0 * (float)(vy1 & vx0);
    float w11 = wy1 * wx1 * (float)(vy1 & vx1);

    int cy0 = min(max(y0, 0), IMH - 1);
    int cy1 = min(max(y1, 0), IMH - 1);
    int cx0 = min(max(x0, 0), IMW - 1);
    int cx1 = min(max(x1, 0), IMW - 1);

    int i00 = cy0 * IMW + cx0;
    int i01 = cy0 * IMW + cx1;
    int i10 = cy1 * IMW + cx0;
    int i11 = cy1 * IMW + cx1;

    const float* xb = x + (size_t)b * CIN * HW;
    // cols[(c*9+kk)][b*HW + hw]
    float* outp = g_cols + (size_t)kk * NDIM + (size_t)b * HW + hw;

    #pragma unroll 4
    for (int c = 0; c < CIN; c++) {
        const float* xc = xb + (size_t)c * HW;
        float v = w00 * xc[i00] + w01 * xc[i01] + w10 * xc[i10] + w11 * xc[i11];
        outp[(size_t)c * (KKTAP * NDIM)] = v;
    }
}

// ---------------------------------------------------------------------------
// Kernel 2: SGEMM  C[M=256][N=16384] = A[256][2304] * g_cols[2304][16384] + bias
// 128x128 block tile, BK=16, 256 threads, 8x8 micro-tile per thread.
// Epilogue writes out[b][o][hw] layout directly.
// ---------------------------------------------------------------------------
#define BM 128
#define BN 128
#define BK 16

__global__ __launch_bounds__(256) void gemm_kernel(
    const float* __restrict__ A,     // weight, [COUT][KDIM] row-major
    const float* __restrict__ bias,  // [COUT]
    float* __restrict__ out)         // [B][COUT][HW]
{
    __shared__ float As[BK][BM];     // transposed A tile
    __shared__ float Bs[BK][BN];

    const int bm  = blockIdx.y * BM;
    const int bn  = blockIdx.x * BN;
    const int tid = threadIdx.x;
    const int tx  = tid & 15;        // 0..15  -> n
    const int ty  = tid >> 4;        // 0..15  -> m

    float acc[8][8];
    #pragma unroll
    for (int i = 0; i < 8; i++)
        #pragma unroll
        for (int j = 0; j < 8; j++) acc[i][j] = 0.0f;

    const float* Bmat = g_cols;

    for (int k0 = 0; k0 < KDIM; k0 += BK) {
        // Load A tile: 128 rows x 16 k -> 512 float4, 2 per thread.
        #pragma unroll
        for (int u = 0; u < 2; u++) {
            int id  = u * 256 + tid;       // 0..511
            int row = id >> 2;             // 0..127
            int kq  = id & 3;              // which float4 within the 16 k
            float4 v = *reinterpret_cast<const float4*>(
                &A[(size_t)(bm + row) * KDIM + k0 + kq * 4]);
            As[kq * 4 + 0][row] = v.x;
            As[kq * 4 + 1][row] = v.y;
            As[kq * 4 + 2][row] = v.z;
            As[kq * 4 + 3][row] = v.w;
        }
        // Load B tile: 16 k x 128 n -> 512 float4, 2 per thread, coalesced.
        #pragma unroll
        for (int u = 0; u < 2; u++) {
            int id = u * 256 + tid;        // 0..511
            int kr = id >> 5;              // 0..15
            int nq = id & 31;              // float4 index within row
            float4 v = *reinterpret_cast<const float4*>(
                &Bmat[(size_t)(k0 + kr) * NDIM + bn + nq * 4]);
            *reinterpret_cast<float4*>(&Bs[kr][nq * 4]) = v;
        }
        __syncthreads();

        #pragma unroll
        for (int k = 0; k < BK; k++) {
            float4 a0 = *reinterpret_cast<const float4*>(&As[k][ty * 8]);
            float4 a1 = *reinterpret_cast<const float4*>(&As[k][ty * 8 + 4]);
            float4 b0 = *reinterpret_cast<const float4*>(&Bs[k][tx * 8]);
            float4 b1 = *reinterpret_cast<const float4*>(&Bs[k][tx * 8 + 4]);
            float a[8] = {a0.x, a0.y, a0.z, a0.w, a1.x, a1.y, a1.z, a1.w};
            float bb[8] = {b0.x, b0.y, b0.z, b0.w, b1.x, b1.y, b1.z, b1.w};
            #pragma unroll
            for (int i = 0; i < 8; i++)
                #pragma unroll
                for (int j = 0; j < 8; j++)
                    acc[i][j] = fmaf(a[i], bb[j], acc[i][j]);
        }
        __syncthreads();
    }

    // Epilogue: n = b*4096 + hw ; tile (BN=128) never crosses a batch boundary.
    const int b_img = bn >> 12;
    const int hw0   = (bn & (HW - 1)) + tx * 8;

    #pragma unroll
    for (int i = 0; i < 8; i++) {
        int m = bm + ty * 8 + i;
        float bv = __ldg(&bias[m]);
        float* orow = out + ((size_t)b_img * COUT + m) * HW + hw0;
        float4 v0 = make_float4(acc[i][0] + bv, acc[i][1] + bv,
                                acc[i][2] + bv, acc[i][3] + bv);
        float4 v1 = make_float4(acc[i][4] + bv, acc[i][5] + bv,
                                acc[i][6] + bv, acc[i][7] + bv);
        *reinterpret_cast<float4*>(orow)     = v0;
        *reinterpret_cast<float4*>(orow + 4) = v1;
    }
}

// ---------------------------------------------------------------------------
extern "C" void kernel_launch(void* const* d_in, const int* in_sizes, int n_in,
                              void* d_out, int out_size)
{
    const float* x      = (const float*)d_in[0];  // [4,256,64,64]
    const float* offset = (const float*)d_in[1];  // [4,18,64,64]
    const float* weight = (const float*)d_in[2];  // [256,256,3,3]
    const float* bias   = (const float*)d_in[3];  // [256]
    float* out = (float*)d_out;                   // [4,256,64,64]

    // B*KK*HW = 147456 taps
    im2col_deform_kernel<<<(BATCH * KKTAP * HW) / 256, 256>>>(x, offset);

    dim3 grid(NDIM / BN, COUT / BM);  // (128, 2)
    gemm_kernel<<<grid, 256>>>(weight, bias, out);
}

// round 5
// speedup vs baseline: 3.0350x; 3.0291x over previous
#include <cuda_runtime.h>
#include <cuda_fp16.h>
#include <cstdint>

#define IMH 64
#define IMW 64
#define HW 4096
#define CIN 256
#define COUT 256
#define KKTAP 9
#define KDIM 2304            // k' = kk*256 + c
#define NDIM 16384

// cols_T: [NDIM][KDIM] fp16 (row = 4608 B = 288 uint4)  — B operand, K-major
__device__ uint4 g_colsT4[(size_t)NDIM * 288];
// repacked weight: [COUT][KDIM] fp16, same k' order     — A operand, K-major
__device__ uint4 g_wr4[(size_t)COUT * 288];

__device__ __forceinline__ uint32_t smem_u32(const void* p) {
    return (uint32_t)__cvta_generic_to_shared(p);
}
__device__ __forceinline__ void cp16(uint32_t d, const void* s) {
    asm volatile("cp.async.cg.shared.global [%0], [%1], 16;" :: "r"(d), "l"(s) : "memory");
}
#define CP_COMMIT() asm volatile("cp.async.commit_group;" ::: "memory")
#define CP_WAIT2()  asm volatile("cp.async.wait_group 2;" ::: "memory")

#define LDSM_X4(r0, r1, r2, r3, a)                                          \
    asm volatile("ldmatrix.sync.aligned.m8n8.x4.shared.b16 {%0,%1,%2,%3}, [%4];" \
                 : "=r"(r0), "=r"(r1), "=r"(r2), "=r"(r3) : "r"(a))

#define MMA16816(c, av, bv0, bv1)                                           \
    asm volatile("mma.sync.aligned.m16n8k16.row.col.f32.f16.f16.f32 "       \
                 "{%0,%1,%2,%3}, {%4,%5,%6,%7}, {%8,%9}, {%0,%1,%2,%3};"    \
                 : "+f"((c)[0]), "+f"((c)[1]), "+f"((c)[2]), "+f"((c)[3])   \
                 : "r"((av)[0]), "r"((av)[1]), "r"((av)[2]), "r"((av)[3]),  \
                   "r"(bv0), "r"(bv1))

// ---------------- Kernel 0: weight repack fp32->fp16, k' = kk*256+c --------
__global__ __launch_bounds__(512) void repack_kernel(const float* __restrict__ w) {
    int idx = blockIdx.x * 512 + threadIdx.x;
    int o = idx / KDIM;
    int r = idx - o * KDIM;
    int kk = r >> 8;
    int c = r & 255;
    reinterpret_cast<__half*>(g_wr4)[idx] = __float2half(w[(o * CIN + c) * KKTAP + kk]);
}

// ---------------- Kernel 1: deformable bilinear gather -> cols_T fp16 ------
// warp = one tap (kk); lanes = 32 consecutive n; 256 channels contiguous/row.
__global__ __launch_bounds__(256) void gather_kernel(const float* __restrict__ x,
                                                     const float* __restrict__ offset) {
    int gw = (blockIdx.x * 256 + threadIdx.x) >> 5;   // < 4608
    int lane = threadIdx.x & 31;
    int kk = gw / 512;
    int n = (gw % 512) * 32 + lane;
    int b = n >> 12;
    int hw = n & 4095;
    int ho = hw >> 6, wo = hw & 63;

    const float* offb = offset + (size_t)b * (2 * KKTAP) * HW;
    float offy = offb[(2 * kk) * HW + hw];
    float offx = offb[(2 * kk + 1) * HW + hw];
    float py = (float)(ho - 1 + kk / 3) + offy;       // stride=1,pad=1,dil=1
    float px = (float)(wo - 1 + kk % 3) + offx;

    float fy = floorf(py), fx = floorf(px);
    float ly = py - fy, lx = px - fx;
    int y0 = (int)fy, x0 = (int)fx, y1 = y0 + 1, x1 = x0 + 1;
    bool vy0 = (y0 >= 0) & (y0 < IMH), vy1 = (y1 >= 0) & (y1 < IMH);
    bool vx0 = (x0 >= 0) & (x0 < IMW), vx1 = (x1 >= 0) & (x1 < IMW);
    float w00 = (1.f - ly) * (1.f - lx) * (float)(vy0 & vx0);
    float w01 = (1.f - ly) * lx * (float)(vy0 & vx1);
    float w10 = ly * (1.f - lx) * (float)(vy1 & vx0);
    float w11 = ly * lx * (float)(vy1 & vx1);
    int cy0 = min(max(y0, 0), IMH - 1), cy1 = min(max(y1, 0), IMH - 1);
    int cx0 = min(max(x0, 0), IMW - 1), cx1 = min(max(x1, 0), IMW - 1);
    int i00 = cy0 * IMW + cx0, i01 = cy0 * IMW + cx1;
    int i10 = cy1 * IMW + cx0, i11 = cy1 * IMW + cx1;

    const float* xb = x + (size_t)b * CIN * HW;
    uint4* orow = g_colsT4 + (size_t)n * 288 + kk * 32;

    #pragma unroll 2
    for (int c8 = 0; c8 < 32; c8++) {
        const float* xc = xb + (size_t)(c8 * 8) * HW;
        uint32_t h[4];
        #pragma unroll
        for (int j = 0; j < 4; j++) {
            float v0 = w00 * xc[i00] + w01 * xc[i01] + w10 * xc[i10] + w11 * xc[i11];
            xc += HW;
            float v1 = w00 * xc[i00] + w01 * xc[i01] + w10 * xc[i10] + w11 * xc[i11];
            xc += HW;
            __half2 hh = __floats2half2_rn(v0, v1);
            h[j] = *reinterpret_cast<uint32_t*>(&hh);
        }
        orow[c8] = make_uint4(h[0], h[1], h[2], h[3]);
    }
}

// ---------------- Kernel 2: HMMA fp16 GEMM (mma.sync m16n8k16) -------------
// C[128m x 128n] CTA tile, BK=32, 4-stage cp.async, 8 warps (warp 32m x 64n).
// SMEM rows padded to 80 B (stride 5x16B, gcd(5,8)=1 => ldmatrix conflict-free)
#define ROWB 80
#define TILEB (128 * ROWB)                 // 10240 B per operand tile
#define STAGEB (2 * TILEB)                 // 20480 B per stage
#define NSTAGE 4
#define KITER (KDIM / 32)                  // 72

__global__ __launch_bounds__(256, 2) void gemm_kernel(const float* __restrict__ bias,
                                                      float* __restrict__ out) {
    extern __shared__ unsigned char smraw[];
    const uint32_t su = smem_u32(smraw);
    const int tid = threadIdx.x;
    const int wid = tid >> 5, lane = tid & 31;
    const int warp_m = wid & 3;            // 4 warps over m (32 each)
    const int warp_n = wid >> 2;           // 2 warps over n (64 each)
    const int bm = blockIdx.y * 128, bn = blockIdx.x * 128;

    const __half* gA0 = reinterpret_cast<const __half*>(g_wr4) + (size_t)bm * KDIM;
    const __half* gB0 = reinterpret_cast<const __half*>(g_colsT4) + (size_t)bn * KDIM;

    // per-thread load slots: 2 x (row, chunk) for A and for B
    const int r0 = tid >> 2, c0 = tid & 3;           // idx = tid
    const int r1 = (256 + tid) >> 2, c1 = c0;        // idx = 256+tid

    auto load_stage = [&](int it, int s) {
        uint32_t sA = su + s * STAGEB;
        uint32_t sB = sA + TILEB;
        const __half* ga = gA0 + it * 32;
        const __half* gb = gB0 + it * 32;
        cp16(sA + r0 * ROWB + c0 * 16, ga + (size_t)r0 * KDIM + c0 * 8);
        cp16(sA + r1 * ROWB + c1 * 16, ga + (size_t)r1 * KDIM + c1 * 8);
        cp16(sB + r0 * ROWB + c0 * 16, gb + (size_t)r0 * KDIM + c0 * 8);
        cp16(sB + r1 * ROWB + c1 * 16, gb + (size_t)r1 * KDIM + c1 * 8);
        CP_COMMIT();
    };

    float acc[2][8][4];
    #pragma unroll
    for (int i = 0; i < 2; i++)
        #pragma unroll
        for (int j = 0; j < 8; j++)
            #pragma unroll
            for (int q = 0; q < 4; q++) acc[i][j][q] = 0.f;

    load_stage(0, 0);
    load_stage(1, 1);
    load_stage(2, 2);
    CP_WAIT2();
    __syncthreads();

    // precomputed ldmatrix lane offsets (bytes within a tile)
    const uint32_t aoff = (uint32_t)(warp_m * 32 + (lane & 15)) * ROWB + ((lane >> 4) << 4);
    const uint32_t boff = (uint32_t)(warp_n * 64 + (lane & 7) + ((lane >> 4) << 3)) * ROWB +
                          (((lane >> 3) & 1) << 4);

    for (int it = 0; it < KITER; it++) {
        if (it + 3 < KITER) load_stage(it + 3, (it + 3) & 3);

        const uint32_t sA = su + (it & 3) * STAGEB;
        const uint32_t sB = sA + TILEB;
        #pragma unroll
        for (int ks = 0; ks < 2; ks++) {
            uint32_t a[2][4], b[8][2];
            #pragma unroll
            for (int mt = 0; mt < 2; mt++)
                LDSM_X4(a[mt][0], a[mt][1], a[mt][2], a[mt][3],
                        sA + aoff + mt * 16 * ROWB + ks * 32);
            #pragma unroll
            for (int nt2 = 0; nt2 < 4; nt2++)
                LDSM_X4(b[2 * nt2][0], b[2 * nt2][1], b[2 * nt2 + 1][0], b[2 * nt2 + 1][1],
                        sB + boff + nt2 * 16 * ROWB + ks * 32);
            #pragma unroll
            for (int mt = 0; mt < 2; mt++)
                #pragma unroll
                for (int nt = 0; nt < 8; nt++)
                    MMA16816(acc[mt][nt], a[mt], b[nt][0], b[nt][1]);
        }
        CP_WAIT2();
        __syncthreads();
    }

    // epilogue: c0=(g,2t) c1=(g,2t+1) c2=(g+8,2t) c3=(g+8,2t+1)
    const int g = lane >> 2, t2 = (lane & 3) * 2;
    const int b_img = bn >> 12;
    const int hw0 = bn & 4095;
    #pragma unroll
    for (int mt = 0; mt < 2; mt++) {
        int m0 = bm + warp_m * 32 + mt * 16 + g;
        float bv0 = __ldg(&bias[m0]);
        float bv1 = __ldg(&bias[m0 + 8]);
        float* row0 = out + ((size_t)b_img * COUT + m0) * HW + hw0;
        float* row1 = row0 + 8 * HW;
        #pragma unroll
        for (int nt = 0; nt < 8; nt++) {
            int nc = warp_n * 64 + nt * 8 + t2;
            *reinterpret_cast<float2*>(row0 + nc) =
                make_float2(acc[mt][nt][0] + bv0, acc[mt][nt][1] + bv0);
            *reinterpret_cast<float2*>(row1 + nc) =
                make_float2(acc[mt][nt][2] + bv1, acc[mt][nt][3] + bv1);
        }
    }
}

// ---------------------------------------------------------------------------
extern "C" void kernel_launch(void* const* d_in, const int* in_sizes, int n_in,
                              void* d_out, int out_size) {
    const float* x      = (const float*)d_in[0];
    const float* offset = (const float*)d_in[1];
    const float* weight = (const float*)d_in[2];
    const float* bias   = (const float*)d_in[3];
    float* out = (float*)d_out;

    repack_kernel<<<COUT * KDIM / 512, 512>>>(weight);
    gather_kernel<<<576, 256>>>(x, offset);

    cudaFuncSetAttribute(gemm_kernel, cudaFuncAttributeMaxDynamicSharedMemorySize,
                         NSTAGE * STAGEB);
    dim3 grid(NDIM / 128, COUT / 128);     // (128, 2)
    gemm_kernel<<<grid, 256, NSTAGE * STAGEB>>>(bias, out);
}

// round 6
// speedup vs baseline: 3.1957x; 1.0530x over previous
#include <cuda_runtime.h>
#include <cuda_fp16.h>
#include <cstdint>

#define IMH 64
#define IMW 64
#define HW 4096
#define CIN 256
#define COUT 256
#define KKTAP 9
#define KDIM 2304            // k' = kk*256 + c
#define NDIM 16384

// cols_T: [NDIM][KDIM] fp16 (row = 4608 B = 288 uint4)  — B operand, K-major
__device__ uint4 g_colsT4[(size_t)NDIM * 288];
// repacked weight: [COUT][KDIM] fp16, same k' order     — A operand, K-major
__device__ uint4 g_wr4[(size_t)COUT * 288];
// packed x: per (b,c,row): words 0..31 = half2(x[2j],x[2j+1]),
//                          words 32..63 = half2(x[2j+1],x[min(2j+2,63)])
__device__ uint32_t g_xh[(size_t)4 * CIN * IMH * 64];

__device__ __forceinline__ uint32_t smem_u32(const void* p) {
    return (uint32_t)__cvta_generic_to_shared(p);
}
__device__ __forceinline__ void cp16(uint32_t d, const void* s) {
    asm volatile("cp.async.cg.shared.global [%0], [%1], 16;" :: "r"(d), "l"(s) : "memory");
}
#define CP_COMMIT() asm volatile("cp.async.commit_group;" ::: "memory")
#define CP_WAIT2()  asm volatile("cp.async.wait_group 2;" ::: "memory")

#define LDSM_X4(r0, r1, r2, r3, a)                                          \
    asm volatile("ldmatrix.sync.aligned.m8n8.x4.shared.b16 {%0,%1,%2,%3}, [%4];" \
                 : "=r"(r0), "=r"(r1), "=r"(r2), "=r"(r3) : "r"(a))

#define MMA16816(c, av, bv0, bv1)                                           \
    asm volatile("mma.sync.aligned.m16n8k16.row.col.f32.f16.f16.f32 "       \
                 "{%0,%1,%2,%3}, {%4,%5,%6,%7}, {%8,%9}, {%0,%1,%2,%3};"    \
                 : "+f"((c)[0]), "+f"((c)[1]), "+f"((c)[2]), "+f"((c)[3])   \
                 : "r"((av)[0]), "r"((av)[1]), "r"((av)[2]), "r"((av)[3]),  \
                   "r"(bv0), "r"(bv1))

// ---------------- Kernel A: pack x fp32 -> parity-pair fp16 planes ---------
// one warp per image row; lane j loads float2 x[2j..2j+1], shfl for x[2j+2]
__global__ __launch_bounds__(256) void xpack_kernel(const float* __restrict__ x) {
    int gw = (blockIdx.x * 256 + threadIdx.x) >> 5;   // row id < 4*256*64
    int j = threadIdx.x & 31;
    const float2 v = reinterpret_cast<const float2*>(x)[(size_t)gw * 32 + j];
    float nx = __shfl_down_sync(0xFFFFFFFFu, v.x, 1);
    if (j == 31) nx = v.y;                            // clamp x[64] -> x[63]
    __half2 we = __floats2half2_rn(v.x, v.y);
    __half2 wo = __floats2half2_rn(v.y, nx);
    uint32_t* row = g_xh + (size_t)gw * 64;
    row[j]      = *reinterpret_cast<uint32_t*>(&we);
    row[32 + j] = *reinterpret_cast<uint32_t*>(&wo);
}

// ---------------- Kernel 0: weight repack fp32->fp16, k' = kk*256+c --------
__global__ __launch_bounds__(512) void repack_kernel(const float* __restrict__ w) {
    int idx = blockIdx.x * 512 + threadIdx.x;
    int o = idx / KDIM;
    int r = idx - o * KDIM;
    int kk = r >> 8;
    int c = r & 255;
    reinterpret_cast<__half*>(g_wr4)[idx] = __float2half(w[(o * CIN + c) * KKTAP + kk]);
}

// ---------------- Kernel 1: deformable gather (pair loads) -> cols_T -------
__global__ __launch_bounds__(256) void gather_kernel(const float* __restrict__ offset) {
    int gw = (blockIdx.x * 256 + threadIdx.x) >> 5;   // < 4608
    int lane = threadIdx.x & 31;
    int kk = gw / 512;
    int n = (gw % 512) * 32 + lane;
    int b = n >> 12;
    int hw = n & 4095;
    int ho = hw >> 6, wo = hw & 63;

    const float* offb = offset + (size_t)b * (2 * KKTAP) * HW;
    float offy = offb[(2 * kk) * HW + hw];
    float offx = offb[(2 * kk + 1) * HW + hw];
    float py = (float)(ho - 1 + kk / 3) + offy;       // stride=1,pad=1,dil=1
    float px = (float)(wo - 1 + kk % 3) + offx;

    float fy = floorf(py), fx = floorf(px);
    float ly = py - fy, lx = px - fx;
    int y0 = (int)fy, x0 = (int)fx, y1 = y0 + 1, x1 = x0 + 1;
    bool vy0 = (y0 >= 0) & (y0 < IMH), vy1 = (y1 >= 0) & (y1 < IMH);
    bool vx0 = (x0 >= 0) & (x0 < IMW), vx1 = (x1 >= 0) & (x1 < IMW);
    float w00 = (1.f - ly) * (1.f - lx) * (float)(vy0 & vx0);
    float w01 = (1.f - ly) * lx * (float)(vy0 & vx1);
    float w10 = ly * (1.f - lx) * (float)(vy1 & vx0);
    float w11 = ly * lx * (float)(vy1 & vx1);

    // pair word covering (x0, x0+1): qx = clamp(x0,0,62)
    int qx = min(max(x0, 0), 62);
    int wq = (qx & 1) ? (32 + (qx >> 1)) : (qx >> 1);
    bool sel0 = (x0 == qx);                            // corner0 in .lo
    bool sel1 = (x1 == qx);                            // corner1 in .lo (x0=-1 case)
    // pre-swap weights onto (lo, hi) lanes of the pair
    float wl0 = sel0 ? w00 : 0.f;  wl0 += sel1 ? w01 : 0.f;
    float wh0 = sel0 ? 0.f : w00;  wh0 += sel1 ? 0.f : w01;
    float wl1 = sel0 ? w10 : 0.f;  wl1 += sel1 ? w11 : 0.f;
    float wh1 = sel0 ? 0.f : w10;  wh1 += sel1 ? 0.f : w11;

    int cy0 = min(max(y0, 0), IMH - 1), cy1 = min(max(y1, 0), IMH - 1);
    const uint32_t* p0 = g_xh + ((size_t)b * CIN * IMH + cy0) * 64 + wq;
    const uint32_t* p1 = g_xh + ((size_t)b * CIN * IMH + cy1) * 64 + wq;

    uint4* orow = g_colsT4 + (size_t)n * 288 + kk * 32;

    #pragma unroll 2
    for (int c8 = 0; c8 < 32; c8++) {
        uint32_t h[4];
        #pragma unroll
        for (int j = 0; j < 4; j++) {
            int c0 = c8 * 8 + j * 2;
            uint32_t a0 = p0[(size_t)(c0)     * (IMH * 64)];
            uint32_t b0 = p1[(size_t)(c0)     * (IMH * 64)];
            uint32_t a1 = p0[(size_t)(c0 + 1) * (IMH * 64)];
            uint32_t b1 = p1[(size_t)(c0 + 1) * (IMH * 64)];
            float2 fa0 = __half22float2(*reinterpret_cast<__half2*>(&a0));
            float2 fb0 = __half22float2(*reinterpret_cast<__half2*>(&b0));
            float2 fa1 = __half22float2(*reinterpret_cast<__half2*>(&a1));
            float2 fb1 = __half22float2(*reinterpret_cast<__half2*>(&b1));
            float v0 = wl0 * fa0.x + wh0 * fa0.y + wl1 * fb0.x + wh1 * fb0.y;
            float v1 = wl0 * fa1.x + wh0 * fa1.y + wl1 * fb1.x + wh1 * fb1.y;
            __half2 hh = __floats2half2_rn(v0, v1);
            h[j] = *reinterpret_cast<uint32_t*>(&hh);
        }
        orow[c8] = make_uint4(h[0], h[1], h[2], h[3]);
    }
}

// ---------------- Kernel 2: HMMA fp16 GEMM (mma.sync m16n8k16) -------------
// CTA tile 64m x 128n, BK=32, 4-stage cp.async, 4 warps (warp 32m x 64n).
#define ROWB 80
#define ATILEB (64 * ROWB)                 // 5120
#define BTILEB (128 * ROWB)                // 10240
#define STAGEB (ATILEB + BTILEB)           // 15360
#define NSTAGE 4
#define KITER (KDIM / 32)                  // 72

__global__ __launch_bounds__(128, 3) void gemm_kernel(const float* __restrict__ bias,
                                                      float* __restrict__ out) {
    extern __shared__ unsigned char smraw[];
    const uint32_t su = smem_u32(smraw);
    const int tid = threadIdx.x;
    const int wid = tid >> 5, lane = tid & 31;
    const int warp_m = wid & 1;            // 2 warps over m (32 each)
    const int warp_n = wid >> 1;           // 2 warps over n (64 each)
    const int bm = blockIdx.y * 64, bn = blockIdx.x * 128;

    const __half* gA0 = reinterpret_cast<const __half*>(g_wr4) + (size_t)bm * KDIM;
    const __half* gB0 = reinterpret_cast<const __half*>(g_colsT4) + (size_t)bn * KDIM;

    auto load_stage = [&](int it, int s) {
        uint32_t sA = su + s * STAGEB;
        uint32_t sB = sA + ATILEB;
        const __half* ga = gA0 + it * 32;
        const __half* gb = gB0 + it * 32;
        #pragma unroll
        for (int i = 0; i < 2; i++) {                 // A: 256 16B-chunks
            int idx = i * 128 + tid, row = idx >> 2, c = idx & 3;
            cp16(sA + row * ROWB + c * 16, ga + (size_t)row * KDIM + c * 8);
        }
        #pragma unroll
        for (int i = 0; i < 4; i++) {                 // B: 512 16B-chunks
            int idx = i * 128 + tid, row = idx >> 2, c = idx & 3;
            cp16(sB + row * ROWB + c * 16, gb + (size_t)row * KDIM + c * 8);
        }
        CP_COMMIT();
    };

    float acc[2][8][4];
    #pragma unroll
    for (int i = 0; i < 2; i++)
        #pragma unroll
        for (int j = 0; j < 8; j++)
            #pragma unroll
            for (int q = 0; q < 4; q++) acc[i][j][q] = 0.f;

    load_stage(0, 0);
    load_stage(1, 1);
    load_stage(2, 2);
    CP_WAIT2();
    __syncthreads();

    const uint32_t aoff = (uint32_t)(warp_m * 32 + (lane & 15)) * ROWB + ((lane >> 4) << 4);
    const uint32_t boff = (uint32_t)(warp_n * 64 + (lane & 7) + ((lane >> 4) << 3)) * ROWB +
                          (((lane >> 3) & 1) << 4);

    for (int it = 0; it < KITER; it++) {
        if (it + 3 < KITER) load_stage(it + 3, (it + 3) & 3);

        const uint32_t sA = su + (it & 3) * STAGEB;
        const uint32_t sB = sA + ATILEB;
        #pragma unroll
        for (int ks = 0; ks < 2; ks++) {
            uint32_t a[2][4], b[8][2];
            #pragma unroll
            for (int mt = 0; mt < 2; mt++)
                LDSM_X4(a[mt][0], a[mt][1], a[mt][2], a[mt][3],
                        sA + aoff + mt * 16 * ROWB + ks * 32);
            #pragma unroll
            for (int nt2 = 0; nt2 < 4; nt2++)
                LDSM_X4(b[2 * nt2][0], b[2 * nt2][1], b[2 * nt2 + 1][0], b[2 * nt2 + 1][1],
                        sB + boff + nt2 * 16 * ROWB + ks * 32);
            #pragma unroll
            for (int mt = 0; mt < 2; mt++)
                #pragma unroll
                for (int nt = 0; nt < 8; nt++)
                    MMA16816(acc[mt][nt], a[mt], b[nt][0], b[nt][1]);
        }
        CP_WAIT2();
        __syncthreads();
    }

    const int g = lane >> 2, t2 = (lane & 3) * 2;
    const int b_img = bn >> 12;
    const int hw0 = bn & 4095;
    #pragma unroll
    for (int mt = 0; mt < 2; mt++) {
        int m0 = bm + warp_m * 32 + mt * 16 + g;
        float bv0 = __ldg(&bias[m0]);
        float bv1 = __ldg(&bias[m0 + 8]);
        float* row0 = out + ((size_t)b_img * COUT + m0) * HW + hw0;
        float* row1 = row0 + 8 * HW;
        #pragma unroll
        for (int nt = 0; nt < 8; nt++) {
            int nc = warp_n * 64 + nt * 8 + t2;
            *reinterpret_cast<float2*>(row0 + nc) =
                make_float2(acc[mt][nt][0] + bv0, acc[mt][nt][1] + bv0);
            *reinterpret_cast<float2*>(row1 + nc) =
                make_float2(acc[mt][nt][2] + bv1, acc[mt][nt][3] + bv1);
        }
    }
}

// ---------------------------------------------------------------------------
extern "C" void kernel_launch(void* const* d_in, const int* in_sizes, int n_in,
                              void* d_out, int out_size) {
    const float* x      = (const float*)d_in[0];
    const float* offset = (const float*)d_in[1];
    const float* weight = (const float*)d_in[2];
    const float* bias   = (const float*)d_in[3];
    float* out = (float*)d_out;

    xpack_kernel<<<(4 * CIN * IMH) / 8, 256>>>(x);          // 8192 blocks
    repack_kernel<<<COUT * KDIM / 512, 512>>>(weight);
    gather_kernel<<<576, 256>>>(offset);

    cudaFuncSetAttribute(gemm_kernel, cudaFuncAttributeMaxDynamicSharedMemorySize,
                         NSTAGE * STAGEB);
    dim3 grid(NDIM / 128, COUT / 64);      // (128, 4) = 512 CTAs
    gemm_kernel<<<grid, 128, NSTAGE * STAGEB>>>(bias, out);
}